// round 4
// baseline (speedup 1.0000x reference)
#include <cuda_runtime.h>

// Not-a-knot cubic spline upsample, B x 8192 fp32 -> B x (8192*ups) fp32.
//
// [1,4,1] tridiagonal inverse = exponential Green's function (lam = sqrt(3)-2),
// composed with the 6*[1,-2,1] rhs into a 17-tap symmetric FIR on y, so the
// second derivatives M are LOCAL. Each CTA handles a 4096-output tile of one
// row:   load y slice -> (FIR M + per-interval cubic coef float4, fused, in
// registers) -> evaluate with 2 LDS.128 + selects + 3 FMA per 4 points.
// Row-boundary tiles additionally compute exact edge M values via truncated
// Green sums and write the first/last ~20 interval coefs themselves.

#define W_DIM  8192
#define NTHR   256
#define TILE_Q 4096
#define KT     8
#define NYMAX  1088
#define SCMAX  1032

#define LAM   (-0.26794919243112270647f)   // sqrt(3) - 2
#define ACOEF (0.28867513459481288225f)    // 1 / (2*sqrt(3))

__device__ __forceinline__ float4 make_coef(float y0, float y1, float m0, float m1) {
    float4 c;
    c.x = y0;
    c.y = fmaf(fmaf(2.f, m0, m1), -(1.f / 6.f), y1 - y0);
    c.z = 0.5f * m0;
    c.w = (m1 - m0) * (1.f / 6.f);
    return c;
}

__global__ __launch_bounds__(NTHR, 5)
void spline_kernel(const float* __restrict__ x, float* __restrict__ out,
                   int nout, float step) {
    __shared__ float4 sC[SCMAX];
    __shared__ float  sy[NYMAX];

    const int tid = threadIdx.x;
    const int row = blockIdx.y;
    const int qbase = blockIdx.x * TILE_Q;
    const int n = W_DIM - 4;

    const float* xr = x + (size_t)row * W_DIM;
    float* outr = out + (size_t)row * nout + qbase;

    // ---- tile geometry ----
    const int imin = (int)((float)qbase * step);
    int imax = (int)((float)(qbase + TILE_Q - 1) * step);
    if (imax > W_DIM - 2) imax = W_DIM - 2;
    int ilo = imin - 12; if (ilo < 0) ilo = 0; ilo &= ~3;
    int ihi = (imax + 17) & ~3; if (ihi > W_DIM) ihi = W_DIM;
    const int NY = ihi - ilo;

    // ---- load y slice (+halo), aligned float4 ----
    {
        const float4* x4 = (const float4*)(xr + ilo);
        float4* sy4 = (float4*)sy;
        for (int v = tid; v < (NY >> 2); v += NTHR) sy4[v] = x4[v];
    }
    __syncthreads();

    // ---- fused FIR + coefficient build (interior intervals) ----
    {
        const float C0 = -4.3923048f;
        const float C[KT] = { 2.7846097f, -0.7461340f, 0.1999261f, -0.0535701f,
                              0.0143541f, -0.0038462f, 0.0010306f, -0.0002761f };
        const int glo = (imin > 20) ? imin : 20;
        const int ghi = (imax < W_DIM - 23) ? imax : (W_DIM - 23);
        const int nchunk = (NY - 24) >> 2;
        for (int c = tid; c < nchunk; c += NTHR) {
            const int li0 = 12 + 4 * c;                 // li0 % 4 == 0
            float win[24];                              // y[li0-8 .. li0+15]
            const float4* wsrc = (const float4*)(sy + li0 - 8);
            #pragma unroll
            for (int v = 0; v < 6; ++v) ((float4*)win)[v] = wsrc[v];
            float M5[5];
            #pragma unroll
            for (int m = 0; m < 5; ++m) {
                float acc = C0 * win[8 + m];
                #pragma unroll
                for (int k = 1; k <= KT; ++k)
                    acc = fmaf(C[k - 1], win[8 + m - k] + win[8 + m + k], acc);
                M5[m] = acc;
            }
            const int gi0 = ilo + li0;
            #pragma unroll
            for (int m = 0; m < 4; ++m) {
                const int gi = gi0 + m;
                if (gi >= glo && gi <= ghi)
                    sC[gi - imin] = make_coef(win[8 + m], win[9 + m], M5[m], M5[m + 1]);
            }
        }
    }

    // ---- left edge (tile containing y[0]): intervals 0..19 ----
    if (ilo == 0 && tid < 20) {
        const float M1 = sy[2] - 2.f * sy[1] + sy[0];
        float SL = 0.f, lp = LAM;
        #pragma unroll 1
        for (int j = 0; j < 24; ++j) {
            float b = 6.f * (sy[j + 3] - 2.f * sy[j + 2] + sy[j + 1]);
            if (j == 0) b -= M1;
            SL = fmaf(lp, b, SL);
            lp *= LAM;
        }
        float Mv[2];
        #pragma unroll 1
        for (int u = 0; u < 2; ++u) {
            const int idx = tid + u;
            if (idx == 1) { Mv[u] = M1; continue; }
            const int jj = (idx == 0) ? 0 : idx - 2;
            float acc = 0.f, p = 1.f;
            #pragma unroll 1
            for (int d = 0; d <= 12; ++d) {
                const int j = jj - d;
                if (j >= 0) {
                    float b = 6.f * (sy[j + 3] - 2.f * sy[j + 2] + sy[j + 1]);
                    if (j == 0) b -= M1;
                    acc = fmaf(p, b, acc);
                }
                p *= LAM;
            }
            p = LAM;
            #pragma unroll 1
            for (int d = 1; d <= 12; ++d) {
                const int j = jj + d;                   // always < n here
                float b = 6.f * (sy[j + 3] - 2.f * sy[j + 2] + sy[j + 1]);
                acc = fmaf(p, b, acc);
                p *= LAM;
            }
            float pw = LAM;                             // lam^{jj+1}
            for (int s = 0; s < jj; ++s) pw *= LAM;
            acc -= pw * SL;
            float v = ACOEF * acc;
            Mv[u] = (idx == 0) ? (2.f * M1 - v) : v;
        }
        sC[tid] = make_coef(sy[tid], sy[tid + 1], Mv[0], Mv[1]);   // imin == 0
    }

    // ---- right edge (tile containing y[W-1]): intervals W-22..W-2 ----
    if (ihi == W_DIM && tid >= 32 && tid < 53) {
        const int t = tid - 32;
        const int gi = (W_DIM - 22) + t;
        const int lW = W_DIM - ilo;
        const float Mn2 = sy[lW - 1] - 2.f * sy[lW - 2] + sy[lW - 3];
        float SR = 0.f, lp = LAM;
        #pragma unroll 1
        for (int m = 0; m < 24; ++m) {
            const int j = n - 1 - m;
            float b = 6.f * (sy[j + 3 - ilo] - 2.f * sy[j + 2 - ilo] + sy[j + 1 - ilo]);
            if (j == n - 1) b -= Mn2;
            SR = fmaf(lp, b, SR);
            lp *= LAM;
        }
        float Mv[2];
        #pragma unroll 1
        for (int u = 0; u < 2; ++u) {
            const int idx = gi + u;
            if (idx == W_DIM - 2) { Mv[u] = Mn2; continue; }
            const int jj = (idx == W_DIM - 1) ? (n - 1) : (idx - 2);
            float acc = 0.f, p = 1.f;
            #pragma unroll 1
            for (int d = 0; d <= 12; ++d) {
                const int j = jj - d;                   // always >= 0 here
                float b = 6.f * (sy[j + 3 - ilo] - 2.f * sy[j + 2 - ilo] + sy[j + 1 - ilo]);
                if (j == n - 1) b -= Mn2;
                acc = fmaf(p, b, acc);
                p *= LAM;
            }
            p = LAM;
            #pragma unroll 1
            for (int d = 1; d <= 12; ++d) {
                const int j = jj + d;
                if (j < n) {
                    float b = 6.f * (sy[j + 3 - ilo] - 2.f * sy[j + 2 - ilo] + sy[j + 1 - ilo]);
                    acc = fmaf(p, b, acc);
                }
                p *= LAM;
            }
            float pw = LAM;                             // lam^{n-jj}
            for (int s = 0; s < n - 1 - jj; ++s) pw *= LAM;
            acc -= pw * SR;
            float v = ACOEF * acc;
            Mv[u] = (idx == W_DIM - 1) ? (2.f * Mn2 - v) : v;
        }
        sC[gi - imin] = make_coef(sy[gi - ilo], sy[gi + 1 - ilo], Mv[0], Mv[1]);
    }
    __syncthreads();

    // ---- evaluate: per 4 points, 2 LDS.128 + selects + 3 FMA each ----
    {
        float4* out4 = (float4*)outr;
        #pragma unroll
        for (int it = 0; it < TILE_Q / (4 * NTHR); ++it) {
            const int qo = 4 * tid + it * (4 * NTHR);
            const int q0 = qbase + qo;
            if (q0 >= nout) break;
            float t4[4]; int i4[4];
            #pragma unroll
            for (int m = 0; m < 4; ++m) {
                const float fq = (float)(q0 + m) * step;
                int i = (int)fq;
                if (i > W_DIM - 2) i = W_DIM - 2;
                t4[m] = fq - (float)i;
                i4[m] = i;
            }
            const int i0 = i4[0];
            const float4 c0 = sC[i0 - imin];
            const float4 c1 = sC[i0 - imin + 1];       // padded, always readable
            float4 r;
            r.x = fmaf(t4[0], fmaf(t4[0], fmaf(t4[0], c0.w, c0.z), c0.y), c0.x);
            #pragma unroll
            for (int m = 1; m < 4; ++m) {
                const bool up = (i4[m] != i0);
                const float cx = up ? c1.x : c0.x;
                const float cy = up ? c1.y : c0.y;
                const float cz = up ? c1.z : c0.z;
                const float cw = up ? c1.w : c0.w;
                ((float*)&r)[m] = fmaf(t4[m], fmaf(t4[m], fmaf(t4[m], cw, cz), cy), cx);
            }
            out4[qo >> 2] = r;
        }
    }
}

extern "C" void kernel_launch(void* const* d_in, const int* in_sizes, int n_in,
                              void* d_out, int out_size) {
    const float* x = (const float*)d_in[0];
    float* out = (float*)d_out;

    const int B = in_sizes[0] / W_DIM;                 // 512
    const int nout = out_size / B;                     // 32768
    const float step = (float)((double)(W_DIM - 1) / (double)(nout - 1));

    dim3 grid((nout + TILE_Q - 1) / TILE_Q, B);        // 8 x 512 = 4096 CTAs
    spline_kernel<<<grid, NTHR>>>(x, out, nout, step);
}

// round 5
// speedup vs baseline: 1.4026x; 1.4026x over previous
#include <cuda_runtime.h>

// Not-a-knot cubic spline upsample, B x 8192 fp32 -> B x (8192*4) fp32.
// [1,4,1] tridiagonal inverse = exponential Green's function (lam = sqrt(3)-2)
// composed with the 6*[1,-2,1] rhs into a 17-tap FIR on y -> M is LOCAL.
// 1024-knot tiles, 256 threads, ~8.5KB smem, 6 CTAs/SM. Two barriers.
// Eval: per 4-output chunk, one floor; both candidate interval coefficient
// sets built in registers; per point 1 predicate + selects + 3 FMA.

#define W_DIM  8192
#define NTHR   256
#define TILE_I 1024
#define KT     8
#define SYN    1064

#define LAM   (-0.26794919243112270647f)   // sqrt(3) - 2
#define ACOEF (0.28867513459481288225f)    // 1 / (2*sqrt(3))

__global__ __launch_bounds__(NTHR, 6)
void spline_kernel(const float* __restrict__ x, float* __restrict__ out,
                   int nout, float step) {
    __shared__ float sy[SYN];
    __shared__ float sM[SYN];

    const int tid = threadIdx.x;
    const int row = blockIdx.y;
    const int kbase = blockIdx.x * TILE_I;          // first knot/chunk of tile
    const int n = W_DIM - 4;

    const float* xr = x + (size_t)row * W_DIM;
    float* outr = out + (size_t)row * nout + kbase * 4;

    int ilo = kbase - 16; if (ilo < 0) ilo = 0;     // multiple of 16
    int ihi = kbase + TILE_I + 16; if (ihi > W_DIM) ihi = W_DIM;
    const int NY = ihi - ilo;

    // ---- load y slice (+halo), aligned float4 ----
    {
        const float4* x4 = (const float4*)(xr + ilo);
        float4* sy4 = (float4*)sy;
        for (int v = tid; v < (NY >> 2); v += NTHR) sy4[v] = x4[v];
    }
    __syncthreads();

    // ---- interior M via 17-tap symmetric FIR on y -> sM ----
    {
        const float C0 = -4.3923048f;
        const float C[KT] = { 2.7846097f, -0.7461340f, 0.1999261f, -0.0535701f,
                              0.0143541f, -0.0038462f, 0.0010306f, -0.0002761f };
        const int FLO = (ilo == 0) ? 20 : 12;       // accuracy floor at row start
        int ghi = kbase + TILE_I;                   // last M needed (interval+1)
        if (ghi > W_DIM - 21) ghi = W_DIM - 21;     // row end handled by edge code
        const int nch = ((ghi - (ilo + FLO)) >> 2) + 1;
        for (int c = tid; c < nch; c += NTHR) {
            const int li0 = FLO + 4 * c;            // li0 % 4 == 0
            float win[20];                          // y[li0-8 .. li0+11]
            const float4* ws = (const float4*)(sy + li0 - 8);
            #pragma unroll
            for (int v = 0; v < 5; ++v) ((float4*)win)[v] = ws[v];
            #pragma unroll
            for (int m = 0; m < 4; ++m) {
                float acc = C0 * win[8 + m];
                #pragma unroll
                for (int k = 1; k <= KT; ++k)
                    acc = fmaf(C[k - 1], win[8 + m - k] + win[8 + m + k], acc);
                if (ilo + li0 + m <= ghi) sM[li0 + m] = acc;
            }
        }
    }

    // ---- left edge (row-start tile): exact M[0..19] via truncated Green sums ----
    if (ilo == 0 && tid < 20) {
        const float M1 = sy[2] - 2.f * sy[1] + sy[0];
        float SL = 0.f, lp = LAM;
        #pragma unroll 4
        for (int j = 0; j < 24; ++j) {
            float b = 6.f * (sy[j + 3] - 2.f * sy[j + 2] + sy[j + 1]);
            if (j == 0) b -= M1;
            SL = fmaf(lp, b, SL);
            lp *= LAM;
        }
        float Mv;
        if (tid == 1) {
            Mv = M1;
        } else {
            const int jj = (tid == 0) ? 0 : tid - 2;
            float acc = 0.f, p = 1.f;
            #pragma unroll 4
            for (int d = 0; d <= 12; ++d) {
                const int j = jj - d;
                if (j >= 0) {
                    float b = 6.f * (sy[j + 3] - 2.f * sy[j + 2] + sy[j + 1]);
                    if (j == 0) b -= M1;
                    acc = fmaf(p, b, acc);
                }
                p *= LAM;
            }
            p = LAM;
            #pragma unroll 4
            for (int d = 1; d <= 12; ++d) {
                const int j = jj + d;                   // always < n
                float b = 6.f * (sy[j + 3] - 2.f * sy[j + 2] + sy[j + 1]);
                acc = fmaf(p, b, acc);
                p *= LAM;
            }
            float pw = LAM;                             // lam^{jj+1}
            for (int s = 0; s < jj; ++s) pw *= LAM;
            acc -= pw * SL;
            Mv = ACOEF * acc;
            if (tid == 0) Mv = 2.f * M1 - Mv;
        }
        sM[tid] = Mv;
    }

    // ---- right edge (row-end tile): exact M[W-20..W-1] ----
    if (ihi == W_DIM && tid >= 32 && tid < 52) {
        const int t = tid - 32;
        const int gi = W_DIM - 20 + t;
        const int lW = W_DIM - ilo;
        const float Mn2 = sy[lW - 1] - 2.f * sy[lW - 2] + sy[lW - 3];
        float SR = 0.f, lp = LAM;
        #pragma unroll 4
        for (int m = 0; m < 24; ++m) {
            const int j = n - 1 - m;
            float b = 6.f * (sy[j + 3 - ilo] - 2.f * sy[j + 2 - ilo] + sy[j + 1 - ilo]);
            if (j == n - 1) b -= Mn2;
            SR = fmaf(lp, b, SR);
            lp *= LAM;
        }
        float Mv;
        if (t == 18) {
            Mv = Mn2;                                   // gi == W-2
        } else {
            const int jj = (t == 19) ? (n - 1) : (gi - 2);
            float acc = 0.f, p = 1.f;
            #pragma unroll 4
            for (int d = 0; d <= 12; ++d) {
                const int j = jj - d;                   // always >= 0
                float b = 6.f * (sy[j + 3 - ilo] - 2.f * sy[j + 2 - ilo] + sy[j + 1 - ilo]);
                if (j == n - 1) b -= Mn2;
                acc = fmaf(p, b, acc);
                p *= LAM;
            }
            p = LAM;
            #pragma unroll 4
            for (int d = 1; d <= 12; ++d) {
                const int j = jj + d;
                if (j < n) {
                    float b = 6.f * (sy[j + 3 - ilo] - 2.f * sy[j + 2 - ilo] + sy[j + 1 - ilo]);
                    acc = fmaf(p, b, acc);
                }
                p *= LAM;
            }
            float pw = LAM;                             // lam^{n-jj}
            for (int s = 0; s < n - 1 - jj; ++s) pw *= LAM;
            acc -= pw * SR;
            Mv = ACOEF * acc;
            if (t == 19) Mv = 2.f * Mn2 - Mv;
        }
        sM[gi - ilo] = Mv;
    }
    __syncthreads();

    // ---- evaluate: 4 chunks/thread, 4 outputs/chunk ----
    {
        float4* out4 = (float4*)outr;
        #pragma unroll
        for (int k = 0; k < TILE_I / NTHR; ++k) {
            const int cl = tid + k * NTHR;              // local chunk
            const int cg = kbase + cl;                  // global chunk
            const float q0f = (float)(4 * cg);
            const float fq0 = q0f * step;               // == reference xq for q=4cg
            int i0 = (int)fq0;
            if (i0 > W_DIM - 2) i0 = W_DIM - 2;
            const float fi0 = (float)i0;
            const int iL = i0 - ilo;

            const float y0 = sy[iL], y1 = sy[iL + 1], y2 = sy[iL + 2];
            const float m0 = sM[iL], m1 = sM[iL + 1], m2 = sM[iL + 2];
            const float Ax = y0;
            const float Ay = fmaf(fmaf(2.f, m0, m1), -(1.f / 6.f), y1 - y0);
            const float Az = 0.5f * m0;
            const float Aw = (m1 - m0) * (1.f / 6.f);
            const float Bx = y1;
            const float By = fmaf(fmaf(2.f, m1, m2), -(1.f / 6.f), y2 - y1);
            const float Bz = 0.5f * m1;
            const float Bw = (m2 - m1) * (1.f / 6.f);
            const bool bval = (i0 < W_DIM - 2);         // interval i0+1 exists

            float4 r;
            {   // point 0: always interval i0 (u < 1 guaranteed)
                const float u = fq0 - fi0;              // Sterbenz-exact == ref t
                r.x = fmaf(u, fmaf(u, fmaf(u, Aw, Az), Ay), Ax);
            }
            #pragma unroll
            for (int m = 1; m < 4; ++m) {
                const float fq = (q0f + (float)m) * step;   // == ref xq bitwise
                const float u = fq - fi0;                   // in [0, 2), exact
                const bool up = (u >= 1.0f) && bval;
                const float t = up ? (u - 1.0f) : u;        // exact either way
                const float cx = up ? Bx : Ax;
                const float cy = up ? By : Ay;
                const float cz = up ? Bz : Az;
                const float cw = up ? Bw : Aw;
                ((float*)&r)[m] = fmaf(t, fmaf(t, fmaf(t, cw, cz), cy), cx);
            }
            out4[cl] = r;
        }
    }
}

extern "C" void kernel_launch(void* const* d_in, const int* in_sizes, int n_in,
                              void* d_out, int out_size) {
    const float* x = (const float*)d_in[0];
    float* out = (float*)d_out;

    const int B = in_sizes[0] / W_DIM;                  // 512
    const int nout = out_size / B;                      // 32768
    const float step = (float)((double)(W_DIM - 1) / (double)(nout - 1));

    dim3 grid(W_DIM / TILE_I, B);                       // 8 x 512 = 4096 CTAs
    spline_kernel<<<grid, NTHR>>>(x, out, nout, step);
}